// round 16
// baseline (speedup 1.0000x reference)
#include <cuda_runtime.h>
#include <cuda_fp16.h>
#include <cstdint>

// Problem constants
#define B_   2
#define SQ_  2048
#define DM_  1024
#define NH_  16
#define DH_  64
#define MROWS (B_*SQ_)                 // 4096
#define HELEMS ((size_t)B_*SQ_*DM_)    // 4M
#define WELEMS ((size_t)NH_*DM_*DH_)   // 1M

// Scratch (no cudaMalloc allowed)
__device__ __half g_qh16[HELEMS], g_ql16[HELEMS];   // post-LN q hi/lo (b,n,s,h)
__device__ __half g_kh16[HELEMS], g_kl16[HELEMS];   // post-LN k hi/lo (b,n,s,h)
__device__ __half g_vh16[HELEMS];                   // v hi (b,n,s,h)
__device__ __half g_zh16[HELEMS], g_zl16[HELEMS];   // attn out hi/lo (b*s, DM)

// ---------------- mma.sync / cp.async helpers ----------------
__device__ __forceinline__ uint32_t smem_u32(const void* p) {
    uint32_t a;
    asm("{ .reg .u64 t; cvta.to.shared.u64 t, %1; cvt.u32.u64 %0, t; }" : "=r"(a) : "l"(p));
    return a;
}
__device__ __forceinline__ void ldsm_x4(uint32_t* r, uint32_t addr) {
    asm volatile("ldmatrix.sync.aligned.m8n8.x4.shared.b16 {%0,%1,%2,%3}, [%4];"
        : "=r"(r[0]), "=r"(r[1]), "=r"(r[2]), "=r"(r[3]) : "r"(addr));
}
__device__ __forceinline__ void ldsm_x4_t(uint32_t* r, uint32_t addr) {
    asm volatile("ldmatrix.sync.aligned.m8n8.x4.trans.shared.b16 {%0,%1,%2,%3}, [%4];"
        : "=r"(r[0]), "=r"(r[1]), "=r"(r[2]), "=r"(r[3]) : "r"(addr));
}
__device__ __forceinline__ void mma_f16(float* d, const uint32_t* a, const uint32_t* b) {
    asm volatile("mma.sync.aligned.m16n8k16.row.col.f32.f16.f16.f32 "
        "{%0,%1,%2,%3}, {%4,%5,%6,%7}, {%8,%9}, {%0,%1,%2,%3};"
        : "+f"(d[0]), "+f"(d[1]), "+f"(d[2]), "+f"(d[3])
        : "r"(a[0]), "r"(a[1]), "r"(a[2]), "r"(a[3]), "r"(b[0]), "r"(b[1]));
}
__device__ __forceinline__ uint32_t pk_f16x2(float lo, float hi) {
    uint32_t d;
    asm("cvt.rn.f16x2.f32 %0, %1, %2;" : "=r"(d) : "f"(hi), "f"(lo));
    return d;
}
__device__ __forceinline__ void cp_async16(uint32_t dst, const void* src) {
    asm volatile("cp.async.cg.shared.global [%0], [%1], 16;" :: "r"(dst), "l"(src));
}
#define CP_COMMIT() asm volatile("cp.async.commit_group;" ::: "memory")

// pack 8 fp32 -> hi uint4 + lo uint4 (halves)
struct HiLo8 { uint4 hi, lo; };
__device__ __forceinline__ HiLo8 split8(float4 v0, float4 v1) {
    HiLo8 r;
    __half2 h0 = __floats2half2_rn(v0.x, v0.y);
    __half2 h1 = __floats2half2_rn(v0.z, v0.w);
    __half2 h2 = __floats2half2_rn(v1.x, v1.y);
    __half2 h3 = __floats2half2_rn(v1.z, v1.w);
    r.hi = make_uint4(*(uint32_t*)&h0, *(uint32_t*)&h1, *(uint32_t*)&h2, *(uint32_t*)&h3);
    __half2 l0 = __floats2half2_rn(v0.x - __low2float(h0), v0.y - __high2float(h0));
    __half2 l1 = __floats2half2_rn(v0.z - __low2float(h1), v0.w - __high2float(h1));
    __half2 l2 = __floats2half2_rn(v1.x - __low2float(h2), v1.y - __high2float(h2));
    __half2 l3 = __floats2half2_rn(v1.z - __low2float(h3), v1.w - __high2float(h3));
    r.lo = make_uint4(*(uint32_t*)&l0, *(uint32_t*)&l1, *(uint32_t*)&l2, *(uint32_t*)&l3);
    return r;
}

// ---------------------------------------------------------------------------
// fp16 tensor-core SGEMM with IN-LOADER fp32->fp16 hi/lo conversion and fused
// bias/LN/split epilogue. (Serial smem loads — cp.async measured slower 2x.)
// Jobs 0 (q) / 1 (k): 3-term (Ah+Al)@Bh + Ah@Bl.
// Job  2 (v):         2-term (Ah+Al)@Bh.
// Job  3 (O-proj):    2-term, A = z fp16 hi/lo from attention.
// ---------------------------------------------------------------------------
#define KC   32
#define STR  40
#define BSTR 136

__global__ void __launch_bounds__(256, 2)
gemm3_kernel(const float* __restrict__ xq, const float* __restrict__ xkv,
             const float* __restrict__ wQ, const float* __restrict__ wK,
             const float* __restrict__ wV, const float* __restrict__ wO,
             const float* __restrict__ bQ, const float* __restrict__ bK,
             const float* __restrict__ bV, const float* __restrict__ bO,
             const float* __restrict__ ln1w, const float* __restrict__ ln1b,
             const float* __restrict__ ln2w, const float* __restrict__ ln2b,
             float* __restrict__ kout, float* __restrict__ vout,
             float* __restrict__ outp, int job_base)
{
    __shared__ __half Ahs[128*STR], Als[128*STR];
    __shared__ __half Bhs[KC*BSTR], Bls[KC*BSTR];

    const int job = job_base + blockIdx.z;
    const float *A32, *B32;
    const float* bias; int hs, rs;
    switch (job) {
        case 0: A32 = xq;  B32 = wQ; bias = bQ; hs = DM_*DH_; rs = DH_; break;
        case 1: A32 = xkv; B32 = wK; bias = bK; hs = DM_*DH_; rs = DH_; break;
        case 2: A32 = xkv; B32 = wV; bias = bV; hs = DM_*DH_; rs = DH_; break;
        default: A32 = nullptr; B32 = wO; bias = bO; hs = DH_; rs = DM_; break;
    }
    const bool use_bl = (job <= 1);

    const int tid  = threadIdx.x;
    const int wid  = tid >> 5;
    const int lane = tid & 31;
    const int bm   = blockIdx.y * 128;
    const int bn   = blockIdx.x * 128;
    const int warp_m = wid & 3;
    const int warp_n = wid >> 2;

    float acc[2][8][4];
    #pragma unroll
    for (int i = 0; i < 2; i++)
        #pragma unroll
        for (int j = 0; j < 8; j++)
            #pragma unroll
            for (int e = 0; e < 4; e++) acc[i][j][e] = 0.f;

    const int a_off   = (lane & 15) * STR + ((lane >> 4) << 3);
    const int b_off_t = ((lane & 7) + (((lane >> 3) & 1) << 3)) * BSTR + ((lane >> 4) << 3);

    for (int k0 = 0; k0 < DM_; k0 += KC) {
        // ---- A tile loaders ----
        if (job == 3) {
            // fp16 hi/lo from attention output
            #pragma unroll
            for (int t = 0; t < 2; t++) {
                int idx = tid + t * 256;
                int m   = idx >> 2;
                int kq  = (idx & 3) << 3;
                size_t ga = (size_t)(bm + m) * DM_ + k0 + kq;
                *(uint4*)&Ahs[m*STR + kq] = *(const uint4*)(g_zh16 + ga);
                *(uint4*)&Als[m*STR + kq] = *(const uint4*)(g_zl16 + ga);
            }
        } else {
            // fp32 input, convert in-loader
            #pragma unroll
            for (int t = 0; t < 2; t++) {
                int idx = tid + t * 256;
                int m   = idx >> 2;
                int kq  = (idx & 3) << 3;
                const float* ap = A32 + (size_t)(bm + m) * DM_ + k0 + kq;
                HiLo8 s = split8(*(const float4*)ap, *(const float4*)(ap + 4));
                *(uint4*)&Ahs[m*STR + kq] = s.hi;
                *(uint4*)&Als[m*STR + kq] = s.lo;
            }
        }
        // ---- B tile loader: fp32 weights, convert in-loader ----
        #pragma unroll
        for (int t = 0; t < 2; t++) {
            int idx = tid + t * 256;
            int k   = idx >> 4;
            int c8  = (idx & 15) << 3;
            int c   = bn + c8;
            const float* bp = B32 + (size_t)(c >> 6) * hs + (size_t)(k0 + k) * rs + (c & 63);
            HiLo8 s = split8(*(const float4*)bp, *(const float4*)(bp + 4));
            *(uint4*)&Bhs[k*BSTR + c8] = s.hi;
            if (use_bl)
                *(uint4*)&Bls[k*BSTR + c8] = s.lo;
        }
        __syncthreads();

        #pragma unroll
        for (int ks = 0; ks < KC; ks += 16) {
            uint32_t ah[2][4], al[2][4], bb[4][4];
            #pragma unroll
            for (int mt = 0; mt < 2; mt++) {
                int b0 = (warp_m*32 + mt*16) * STR + ks;
                ldsm_x4(ah[mt], smem_u32(&Ahs[b0 + a_off]));
                ldsm_x4(al[mt], smem_u32(&Als[b0 + a_off]));
            }
            #pragma unroll
            for (int nb = 0; nb < 4; nb++) {
                int b0 = ks*BSTR + warp_n*64 + nb*16;
                ldsm_x4_t(bb[nb], smem_u32(&Bhs[b0 + b_off_t]));
            }
            #pragma unroll
            for (int mt = 0; mt < 2; mt++)
                #pragma unroll
                for (int nt = 0; nt < 8; nt++) {
                    mma_f16(acc[mt][nt], ah[mt], &bb[nt>>1][(nt&1)*2]);
                    mma_f16(acc[mt][nt], al[mt], &bb[nt>>1][(nt&1)*2]);
                }
            if (use_bl) {
                #pragma unroll
                for (int nb = 0; nb < 4; nb++) {
                    int b0 = ks*BSTR + warp_n*64 + nb*16;
                    ldsm_x4_t(bb[nb], smem_u32(&Bls[b0 + b_off_t]));
                }
                #pragma unroll
                for (int mt = 0; mt < 2; mt++)
                    #pragma unroll
                    for (int nt = 0; nt < 8; nt++)
                        mma_f16(acc[mt][nt], ah[mt], &bb[nt>>1][(nt&1)*2]);
            }
        }
        __syncthreads();
    }

    // ---------------- fused epilogue ----------------
    if (job == 3) {
        #pragma unroll
        for (int mt = 0; mt < 2; mt++) {
            int r0 = bm + warp_m*32 + mt*16 + (lane >> 2);
            #pragma unroll
            for (int nt = 0; nt < 8; nt++) {
                int col = bn + warp_n*64 + nt*8 + (lane & 3)*2;
                float b0 = __ldg(bias + col), b1 = __ldg(bias + col + 1);
                float2 o0 = { acc[mt][nt][0] + b0, acc[mt][nt][1] + b1 };
                float2 o1 = { acc[mt][nt][2] + b0, acc[mt][nt][3] + b1 };
                *(float2*)(outp + (size_t)r0       * DM_ + col) = o0;
                *(float2*)(outp + (size_t)(r0 + 8) * DM_ + col) = o1;
            }
        }
        return;
    }

    // QKV: bias + (LN) + fp16 split, head-major writeout.
    const int n = (bn >> 6) + warp_n;
    const float* lw = (job == 0) ? ln1w : ln2w;
    const float* lb = (job == 0) ? ln1b : ln2b;
    __half* dsth = (job == 0) ? g_qh16 : (job == 1) ? g_kh16 : g_vh16;
    __half* dstl = (job == 0) ? g_ql16 : g_kl16;
    float*  cf   = (job == 1) ? kout : vout;

    #pragma unroll
    for (int mt = 0; mt < 2; mt++) {
        #pragma unroll
        for (int rh = 0; rh < 2; rh++) {
            const int row = bm + warp_m*32 + mt*16 + (lane >> 2) + rh*8;
            const int bb_ = row >> 11;
            const int s   = row & (SQ_ - 1);
            const size_t hbase = (((size_t)(bb_ * NH_ + n)) * SQ_ + s) * DH_;

            float vals[16];
            float sum = 0.f, sq = 0.f;
            #pragma unroll
            for (int nt = 0; nt < 8; nt++) {
                int col = bn + warp_n*64 + nt*8 + (lane & 3)*2;
                float v0 = acc[mt][nt][rh*2+0] + __ldg(bias + col);
                float v1 = acc[mt][nt][rh*2+1] + __ldg(bias + col + 1);
                vals[nt*2]   = v0;
                vals[nt*2+1] = v1;
                sum += v0 + v1;
                sq  += v0*v0 + v1*v1;
            }

            if (job < 2) {
                sum += __shfl_xor_sync(0xffffffffu, sum, 1);
                sum += __shfl_xor_sync(0xffffffffu, sum, 2);
                sq  += __shfl_xor_sync(0xffffffffu, sq, 1);
                sq  += __shfl_xor_sync(0xffffffffu, sq, 2);
                float mean = sum * (1.0f/64.0f);
                float var  = sq * (1.0f/64.0f) - mean*mean;
                float rstd = rsqrtf(var + 1e-5f);
                #pragma unroll
                for (int nt = 0; nt < 8; nt++) {
                    int h = nt*8 + (lane & 3)*2;
                    vals[nt*2]   = (vals[nt*2]   - mean) * rstd * __ldg(lw + h)     + __ldg(lb + h);
                    vals[nt*2+1] = (vals[nt*2+1] - mean) * rstd * __ldg(lw + h + 1) + __ldg(lb + h + 1);
                }
            }

            #pragma unroll
            for (int nt = 0; nt < 8; nt++) {
                int h = nt*8 + (lane & 3)*2;
                float v0 = vals[nt*2], v1 = vals[nt*2+1];
                __half2 hh = __floats2half2_rn(v0, v1);
                *(__half2*)(dsth + hbase + h) = hh;
                if (job < 2) {
                    *(__half2*)(dstl + hbase + h) =
                        __floats2half2_rn(v0 - __low2float(hh), v1 - __high2float(hh));
                }
                if (job >= 1) {
                    float2 o = { v0, v1 };
                    *(float2*)(cf + (size_t)row * DM_ + bn + warp_n*64 + h) = o;
                }
            }
        }
    }
}

// ---------------------------------------------------------------------------
// Tensor-core causal flash attention (R12-proven: LPT + cp.async dbl buffer).
// ---------------------------------------------------------------------------
#define ASTR 72
#define TILEH (64*ASTR)
#define ASTAGE (3*TILEH)
#define ATTN_SMEM_BYTES (2*ASTAGE*2)   // 55296 bytes

__global__ void __launch_bounds__(128, 3)
attn_mma_kernel()
{
    extern __shared__ __half asmem[];

    const int tid  = threadIdx.x;
    const int wid  = tid >> 5;
    const int lane = tid & 31;
    const int qb = (int)gridDim.x - 1 - (int)blockIdx.x;   // LPT: heavy first
    const int n = blockIdx.y, b = blockIdx.z;
    const size_t hoff = ((size_t)(b * NH_ + n)) * SQ_ * DH_;

    const int a_off = (lane & 15) * ASTR + ((lane >> 4) << 3);
    const int b_off = ((lane & 7) + ((lane >> 4) << 3)) * ASTR + (((lane >> 3) & 1) << 3);
    const int v_off = ((lane & 7) + (((lane >> 3) & 1) << 3)) * ASTR + ((lane >> 4) << 3);

    uint32_t qfh[4][4], qfl[4][4];
    {
        const __half* qhp = g_qh16 + hoff + (size_t)qb * 64 * DH_;
        const __half* qlp = g_ql16 + hoff + (size_t)qb * 64 * DH_;
        #pragma unroll
        for (int i = 0; i < 4; i++) {
            int idx = tid + i * 128;
            int r = idx >> 3, c8 = (idx & 7) << 3;
            *(uint4*)&asmem[r*ASTR + c8]         = *(const uint4*)(qhp + (size_t)r * DH_ + c8);
            *(uint4*)&asmem[TILEH + r*ASTR + c8] = *(const uint4*)(qlp + (size_t)r * DH_ + c8);
        }
        __syncthreads();
        #pragma unroll
        for (int ks = 0; ks < 4; ks++) {
            ldsm_x4(qfh[ks], smem_u32(&asmem[(wid*16)*ASTR + ks*16 + a_off]));
            ldsm_x4(qfl[ks], smem_u32(&asmem[TILEH + (wid*16)*ASTR + ks*16 + a_off]));
        }
        __syncthreads();
    }

    const int ntiles = qb + 1;

    auto load_tile = [&](int kt, int st) {
        __half* base = asmem + st * ASTAGE;
        const __half* khp = g_kh16 + hoff + (size_t)kt * 64 * DH_;
        const __half* klp = g_kl16 + hoff + (size_t)kt * 64 * DH_;
        const __half* vhp = g_vh16 + hoff + (size_t)kt * 64 * DH_;
        #pragma unroll
        for (int i = 0; i < 4; i++) {
            int idx = tid + i * 128;
            int r = idx >> 3, c8 = (idx & 7) << 3;
            size_t go = (size_t)r * DH_ + c8;
            uint32_t so = smem_u32(base + r*ASTR + c8);
            cp_async16(so,             khp + go);
            cp_async16(so + TILEH*2,   klp + go);
            cp_async16(so + 2*TILEH*2, vhp + go);
        }
        CP_COMMIT();
    };

    float oacc[8][4];
    #pragma unroll
    for (int i = 0; i < 8; i++)
        #pragma unroll
        for (int e = 0; e < 4; e++) oacc[i][e] = 0.f;
    float m0 = -1e30f, m1 = -1e30f, l0 = 0.f, l1 = 0.f;

    const int rg0 = qb*64 + wid*16 + (lane >> 2);

    load_tile(0, 0);

    for (int kt = 0; kt < ntiles; kt++) {
        const int st = kt & 1;
        if (kt + 1 < ntiles) {
            load_tile(kt + 1, st ^ 1);
            asm volatile("cp.async.wait_group 1;" ::: "memory");
        } else {
            asm volatile("cp.async.wait_group 0;" ::: "memory");
        }
        __syncthreads();

        __half* Ksh = asmem + st * ASTAGE;
        __half* Ksl = Ksh + TILEH;
        __half* Vsh = Ksh + 2*TILEH;

        float sacc[8][4];
        #pragma unroll
        for (int i = 0; i < 8; i++)
            #pragma unroll
            for (int e = 0; e < 4; e++) sacc[i][e] = 0.f;

        #pragma unroll
        for (int ks = 0; ks < 4; ks++) {
            #pragma unroll
            for (int nbp = 0; nbp < 4; nbp++) {
                uint32_t kh4[4], kl4[4];
                ldsm_x4(kh4, smem_u32(&Ksh[(nbp*16)*ASTR + ks*16 + b_off]));
                ldsm_x4(kl4, smem_u32(&Ksl[(nbp*16)*ASTR + ks*16 + b_off]));
                #pragma unroll
                for (int h = 0; h < 2; h++) {
                    int nb = nbp*2 + h;
                    mma_f16(sacc[nb], qfh[ks], &kh4[h*2]);
                    mma_f16(sacc[nb], qfl[ks], &kh4[h*2]);
                    mma_f16(sacc[nb], qfh[ks], &kl4[h*2]);
                }
            }
        }

        if (kt == qb) {
            #pragma unroll
            for (int nb = 0; nb < 8; nb++) {
                int j = kt*64 + nb*8 + (lane & 3)*2;
                if (j     > rg0)     sacc[nb][0] = -1e30f;
                if (j + 1 > rg0)     sacc[nb][1] = -1e30f;
                if (j     > rg0 + 8) sacc[nb][2] = -1e30f;
                if (j + 1 > rg0 + 8) sacc[nb][3] = -1e30f;
            }
        }

        float t0 = -1e30f, t1 = -1e30f;
        #pragma unroll
        for (int nb = 0; nb < 8; nb++) {
            t0 = fmaxf(t0, fmaxf(sacc[nb][0], sacc[nb][1]));
            t1 = fmaxf(t1, fmaxf(sacc[nb][2], sacc[nb][3]));
        }
        t0 = fmaxf(t0, __shfl_xor_sync(0xffffffffu, t0, 1));
        t0 = fmaxf(t0, __shfl_xor_sync(0xffffffffu, t0, 2));
        t1 = fmaxf(t1, __shfl_xor_sync(0xffffffffu, t1, 1));
        t1 = fmaxf(t1, __shfl_xor_sync(0xffffffffu, t1, 2));
        float mn0 = fmaxf(m0, t0), mn1 = fmaxf(m1, t1);
        float c0 = __expf(m0 - mn0), c1 = __expf(m1 - mn1);
        m0 = mn0; m1 = mn1;

        uint32_t pah[4][4], pal[4][4];
        float rs0 = 0.f, rs1 = 0.f;
        #pragma unroll
        for (int nb = 0; nb < 8; nb++) {
            float p0 = __expf(sacc[nb][0] - mn0);
            float p1 = __expf(sacc[nb][1] - mn0);
            float p2 = __expf(sacc[nb][2] - mn1);
            float p3 = __expf(sacc[nb][3] - mn1);
            rs0 += p0 + p1; rs1 += p2 + p3;
            __half h0 = __float2half_rn(p0), h1 = __float2half_rn(p1);
            __half h2 = __float2half_rn(p2), h3 = __float2half_rn(p3);
            float q0 = p0 - __half2float(h0), q1 = p1 - __half2float(h1);
            float q2 = p2 - __half2float(h2), q3 = p3 - __half2float(h3);
            int ks = nb >> 1, sel = (nb & 1) * 2;
            pah[ks][sel]     = pk_f16x2(__half2float(h0), __half2float(h1));
            pah[ks][sel + 1] = pk_f16x2(__half2float(h2), __half2float(h3));
            pal[ks][sel]     = pk_f16x2(q0, q1);
            pal[ks][sel + 1] = pk_f16x2(q2, q3);
        }
        rs0 += __shfl_xor_sync(0xffffffffu, rs0, 1);
        rs0 += __shfl_xor_sync(0xffffffffu, rs0, 2);
        rs1 += __shfl_xor_sync(0xffffffffu, rs1, 1);
        rs1 += __shfl_xor_sync(0xffffffffu, rs1, 2);
        l0 = l0 * c0 + rs0;
        l1 = l1 * c1 + rs1;
        #pragma unroll
        for (int nb = 0; nb < 8; nb++) {
            oacc[nb][0] *= c0; oacc[nb][1] *= c0;
            oacc[nb][2] *= c1; oacc[nb][3] *= c1;
        }

        #pragma unroll
        for (int ks = 0; ks < 4; ks++) {
            #pragma unroll
            for (int nbp = 0; nbp < 4; nbp++) {
                uint32_t vh4[4];
                ldsm_x4_t(vh4, smem_u32(&Vsh[(ks*16)*ASTR + nbp*16 + v_off]));
                #pragma unroll
                for (int h = 0; h < 2; h++) {
                    int nb = nbp*2 + h;
                    mma_f16(oacc[nb], pah[ks], &vh4[h*2]);
                    mma_f16(oacc[nb], pal[ks], &vh4[h*2]);
                }
            }
        }
        __syncthreads();
    }

    float i0 = 1.0f / l0, i1 = 1.0f / l1;
    const int s0 = rg0;
    #pragma unroll
    for (int nb = 0; nb < 8; nb++) {
        int h = nb*8 + (lane & 3)*2;
        size_t z0 = (size_t)(b*SQ_ + s0    ) * DM_ + n*DH_ + h;
        size_t z1 = (size_t)(b*SQ_ + s0 + 8) * DM_ + n*DH_ + h;
        float a0 = oacc[nb][0] * i0, a1 = oacc[nb][1] * i0;
        float a2 = oacc[nb][2] * i1, a3 = oacc[nb][3] * i1;
        __half2 hh0 = __floats2half2_rn(a0, a1);
        __half2 hh1 = __floats2half2_rn(a2, a3);
        *(__half2*)(g_zh16 + z0) = hh0;
        *(__half2*)(g_zh16 + z1) = hh1;
        *(__half2*)(g_zl16 + z0) = __floats2half2_rn(a0 - __low2float(hh0), a1 - __high2float(hh0));
        *(__half2*)(g_zl16 + z1) = __floats2half2_rn(a2 - __low2float(hh1), a3 - __high2float(hh1));
    }
}

// ---------------------------------------------------------------------------
// Launch. Inputs: 0 x_q, 1 x_kv, 2 mask(ignored), 3 W_Q, 4 W_K, 5 W_V, 6 W_O,
// 7 b_Q, 8 b_K, 9 b_V, 10 b_O, 11 ln1_w, 12 ln1_b, 13 ln2_w, 14 ln2_b
// Output: [out (B,SQ,DM) | k_postLN (B,SK,NH,DH) | v (B,SK,NH,DH)]
// ---------------------------------------------------------------------------
extern "C" void kernel_launch(void* const* d_in, const int* in_sizes, int n_in,
                              void* d_out, int out_size)
{
    const float* x_q  = (const float*)d_in[0];
    const float* x_kv = (const float*)d_in[1];
    const float* W_Q  = (const float*)d_in[3];
    const float* W_K  = (const float*)d_in[4];
    const float* W_V  = (const float*)d_in[5];
    const float* W_O  = (const float*)d_in[6];
    const float* b_Q  = (const float*)d_in[7];
    const float* b_K  = (const float*)d_in[8];
    const float* b_V  = (const float*)d_in[9];
    const float* b_O  = (const float*)d_in[10];
    const float* ln1w = (const float*)d_in[11];
    const float* ln1b = (const float*)d_in[12];
    const float* ln2w = (const float*)d_in[13];
    const float* ln2b = (const float*)d_in[14];

    float* out  = (float*)d_out;
    float* kout = out  + HELEMS;
    float* vout = kout + HELEMS;

    cudaFuncSetAttribute(attn_mma_kernel, cudaFuncAttributeMaxDynamicSharedMemorySize,
                         ATTN_SMEM_BYTES);

    // Merged QKV projections; fp32->fp16 conversion fused into loaders.
    gemm3_kernel<<<dim3(DM_/128, MROWS/128, 3), 256>>>(
        x_q, x_kv, W_Q, W_K, W_V, W_O, b_Q, b_K, b_V, b_O,
        ln1w, ln1b, ln2w, ln2b, kout, vout, out, 0);

    // Causal attention -> z fp16 hi/lo (LPT + double-buffered tiles)
    attn_mma_kernel<<<dim3(SQ_/64, NH_, B_), 128, ATTN_SMEM_BYTES>>>();

    // Output projection (+b_O), 2-term.
    gemm3_kernel<<<dim3(DM_/128, MROWS/128, 1), 256>>>(
        x_q, x_kv, W_Q, W_K, W_V, W_O, b_Q, b_K, b_V, b_O,
        ln1w, ln1b, ln2w, ln2b, kout, vout, out, 3);
}

// round 17
// speedup vs baseline: 1.0868x; 1.0868x over previous
#include <cuda_runtime.h>
#include <cuda_fp16.h>
#include <cstdint>

// Problem constants
#define B_   2
#define SQ_  2048
#define DM_  1024
#define NH_  16
#define DH_  64
#define MROWS (B_*SQ_)                 // 4096
#define HELEMS ((size_t)B_*SQ_*DM_)    // 4M
#define WELEMS ((size_t)NH_*DM_*DH_)   // 1M

// Scratch (no cudaMalloc allowed)
__device__ __half g_xqh[HELEMS],  g_xql[HELEMS];
__device__ __half g_xkvh[HELEMS], g_xkvl[HELEMS];
__device__ __half g_wqh[WELEMS], g_wql[WELEMS];
__device__ __half g_wkh[WELEMS], g_wkl[WELEMS];
__device__ __half g_wvh[WELEMS];
__device__ __half g_woh[WELEMS];
__device__ __half g_qh16[HELEMS], g_ql16[HELEMS];   // post-LN q hi/lo (b,n,s,h)
__device__ __half g_kh16[HELEMS], g_kl16[HELEMS];   // post-LN k hi/lo (b,n,s,h)
__device__ __half g_vh16[HELEMS];                   // v hi (b,n,s,h)
__device__ __half g_zh16[HELEMS];                   // attn out hi (b*s, DM)

// ---------------- mma.sync / cp.async helpers ----------------
__device__ __forceinline__ uint32_t smem_u32(const void* p) {
    uint32_t a;
    asm("{ .reg .u64 t; cvta.to.shared.u64 t, %1; cvt.u32.u64 %0, t; }" : "=r"(a) : "l"(p));
    return a;
}
__device__ __forceinline__ void ldsm_x4(uint32_t* r, uint32_t addr) {
    asm volatile("ldmatrix.sync.aligned.m8n8.x4.shared.b16 {%0,%1,%2,%3}, [%4];"
        : "=r"(r[0]), "=r"(r[1]), "=r"(r[2]), "=r"(r[3]) : "r"(addr));
}
__device__ __forceinline__ void ldsm_x4_t(uint32_t* r, uint32_t addr) {
    asm volatile("ldmatrix.sync.aligned.m8n8.x4.trans.shared.b16 {%0,%1,%2,%3}, [%4];"
        : "=r"(r[0]), "=r"(r[1]), "=r"(r[2]), "=r"(r[3]) : "r"(addr));
}
__device__ __forceinline__ void mma_f16(float* d, const uint32_t* a, const uint32_t* b) {
    asm volatile("mma.sync.aligned.m16n8k16.row.col.f32.f16.f16.f32 "
        "{%0,%1,%2,%3}, {%4,%5,%6,%7}, {%8,%9}, {%0,%1,%2,%3};"
        : "+f"(d[0]), "+f"(d[1]), "+f"(d[2]), "+f"(d[3])
        : "r"(a[0]), "r"(a[1]), "r"(a[2]), "r"(a[3]), "r"(b[0]), "r"(b[1]));
}
__device__ __forceinline__ uint32_t pk_f16x2(float lo, float hi) {
    uint32_t d;
    asm("cvt.rn.f16x2.f32 %0, %1, %2;" : "=r"(d) : "f"(hi), "f"(lo));
    return d;
}
__device__ __forceinline__ void cp_async16(uint32_t dst, const void* src) {
    asm volatile("cp.async.cg.shared.global [%0], [%1], 16;" :: "r"(dst), "l"(src));
}
#define CP_COMMIT() asm volatile("cp.async.commit_group;" ::: "memory")

// ---------------------------------------------------------------------------
// Prep: fp32 -> fp16 splits. x_q/x_kv/W_Q/W_K get hi+lo; W_V/W_O hi only.
// ---------------------------------------------------------------------------
__global__ void __launch_bounds__(256)
prep_split(const float* __restrict__ xq, const float* __restrict__ xkv,
           const float* __restrict__ wq, const float* __restrict__ wk,
           const float* __restrict__ wv, const float* __restrict__ wo)
{
    const int job = blockIdx.y;
    const float* src; __half* dh; __half* dl; size_t n4;
    switch (job) {
        case 0: src = xq;  dh = g_xqh;  dl = g_xql;  n4 = HELEMS/4; break;
        case 1: src = xkv; dh = g_xkvh; dl = g_xkvl; n4 = HELEMS/4; break;
        case 2: src = wq;  dh = g_wqh;  dl = g_wql;  n4 = WELEMS/4; break;
        case 3: src = wk;  dh = g_wkh;  dl = g_wkl;  n4 = WELEMS/4; break;
        case 4: src = wv;  dh = g_wvh;  dl = nullptr; n4 = WELEMS/4; break;
        default: src = wo; dh = g_woh;  dl = nullptr; n4 = WELEMS/4; break;
    }
    for (size_t i = (size_t)blockIdx.x * 256 + threadIdx.x; i < n4;
         i += (size_t)gridDim.x * 256) {
        float4 v = ((const float4*)src)[i];
        __half2 h01 = __floats2half2_rn(v.x, v.y);
        __half2 h23 = __floats2half2_rn(v.z, v.w);
        *(__half2*)(dh + 4*i)     = h01;
        *(__half2*)(dh + 4*i + 2) = h23;
        if (dl) {
            float r0 = v.x - __low2float(h01), r1 = v.y - __high2float(h01);
            float r2 = v.z - __low2float(h23), r3 = v.w - __high2float(h23);
            *(__half2*)(dl + 4*i)     = __floats2half2_rn(r0, r1);
            *(__half2*)(dl + 4*i + 2) = __floats2half2_rn(r2, r3);
        }
    }
}

// ---------------------------------------------------------------------------
// fp16 tensor-core SGEMM with fused bias/LN/split epilogue.
// (Serial smem loads — cp.async measured slower twice; in-loader fp32 cvt
//  measured slower once. Keep pre-split fp16 inputs.)
// Jobs 0 (q) / 1 (k): 3-term (Ah+Al)@Bh + Ah@Bl.
// Job  2 (v):         1-term Ah@Bh  (x-lo and w-lo dropped; error budget ok).
// Job  3 (O-proj):    1-term zh@Wh.
// ---------------------------------------------------------------------------
#define KC   32
#define STR  40
#define BSTR 136

__global__ void __launch_bounds__(256, 2)
gemm3_kernel(const float* __restrict__ bQ, const float* __restrict__ bK,
             const float* __restrict__ bV, const float* __restrict__ bO,
             const float* __restrict__ ln1w, const float* __restrict__ ln1b,
             const float* __restrict__ ln2w, const float* __restrict__ ln2b,
             float* __restrict__ kout, float* __restrict__ vout,
             float* __restrict__ outp, int job_base)
{
    __shared__ __half Ahs[128*STR], Als[128*STR];
    __shared__ __half Bhs[KC*BSTR], Bls[KC*BSTR];

    const int job = job_base + blockIdx.z;
    const __half *Ahg, *Alg, *Bhg, *Blg;
    const float* bias; int hs, rs;
    switch (job) {
        case 0: Ahg = g_xqh;  Alg = g_xql;  Bhg = g_wqh; Blg = g_wql;
                bias = bQ; hs = DM_*DH_; rs = DH_; break;
        case 1: Ahg = g_xkvh; Alg = g_xkvl; Bhg = g_wkh; Blg = g_wkl;
                bias = bK; hs = DM_*DH_; rs = DH_; break;
        case 2: Ahg = g_xkvh; Alg = nullptr; Bhg = g_wvh; Blg = nullptr;
                bias = bV; hs = DM_*DH_; rs = DH_; break;
        default: Ahg = g_zh16; Alg = nullptr; Bhg = g_woh; Blg = nullptr;
                bias = bO; hs = DH_; rs = DM_; break;
    }
    const bool use_bl = (job <= 1);
    const bool use_al = (job <= 1);

    const int tid  = threadIdx.x;
    const int wid  = tid >> 5;
    const int lane = tid & 31;
    const int bm   = blockIdx.y * 128;
    const int bn   = blockIdx.x * 128;
    const int warp_m = wid & 3;
    const int warp_n = wid >> 2;

    float acc[2][8][4];
    #pragma unroll
    for (int i = 0; i < 2; i++)
        #pragma unroll
        for (int j = 0; j < 8; j++)
            #pragma unroll
            for (int e = 0; e < 4; e++) acc[i][j][e] = 0.f;

    const int a_off   = (lane & 15) * STR + ((lane >> 4) << 3);
    const int b_off_t = ((lane & 7) + (((lane >> 3) & 1) << 3)) * BSTR + ((lane >> 4) << 3);

    for (int k0 = 0; k0 < DM_; k0 += KC) {
        #pragma unroll
        for (int t = 0; t < 2; t++) {
            int idx = tid + t * 256;
            int m   = idx >> 2;
            int kq  = (idx & 3) << 3;
            size_t ga = (size_t)(bm + m) * DM_ + k0 + kq;
            *(uint4*)&Ahs[m*STR + kq] = *(const uint4*)(Ahg + ga);
            if (use_al)
                *(uint4*)&Als[m*STR + kq] = *(const uint4*)(Alg + ga);
        }
        #pragma unroll
        for (int t = 0; t < 2; t++) {
            int idx = tid + t * 256;
            int k   = idx >> 4;
            int c8  = (idx & 15) << 3;
            int c   = bn + c8;
            size_t off = (size_t)(c >> 6) * hs + (size_t)(k0 + k) * rs + (c & 63);
            *(uint4*)&Bhs[k*BSTR + c8] = *(const uint4*)(Bhg + off);
            if (use_bl)
                *(uint4*)&Bls[k*BSTR + c8] = *(const uint4*)(Blg + off);
        }
        __syncthreads();

        #pragma unroll
        for (int ks = 0; ks < KC; ks += 16) {
            uint32_t ah[2][4], al[2][4], bb[4][4];
            #pragma unroll
            for (int mt = 0; mt < 2; mt++) {
                int b0 = (warp_m*32 + mt*16) * STR + ks;
                ldsm_x4(ah[mt], smem_u32(&Ahs[b0 + a_off]));
                if (use_al)
                    ldsm_x4(al[mt], smem_u32(&Als[b0 + a_off]));
            }
            #pragma unroll
            for (int nb = 0; nb < 4; nb++) {
                int b0 = ks*BSTR + warp_n*64 + nb*16;
                ldsm_x4_t(bb[nb], smem_u32(&Bhs[b0 + b_off_t]));
            }
            #pragma unroll
            for (int mt = 0; mt < 2; mt++)
                #pragma unroll
                for (int nt = 0; nt < 8; nt++) {
                    mma_f16(acc[mt][nt], ah[mt], &bb[nt>>1][(nt&1)*2]);
                    if (use_al)
                        mma_f16(acc[mt][nt], al[mt], &bb[nt>>1][(nt&1)*2]);
                }
            if (use_bl) {
                #pragma unroll
                for (int nb = 0; nb < 4; nb++) {
                    int b0 = ks*BSTR + warp_n*64 + nb*16;
                    ldsm_x4_t(bb[nb], smem_u32(&Bls[b0 + b_off_t]));
                }
                #pragma unroll
                for (int mt = 0; mt < 2; mt++)
                    #pragma unroll
                    for (int nt = 0; nt < 8; nt++)
                        mma_f16(acc[mt][nt], ah[mt], &bb[nt>>1][(nt&1)*2]);
            }
        }
        __syncthreads();
    }

    // ---------------- fused epilogue ----------------
    if (job == 3) {
        #pragma unroll
        for (int mt = 0; mt < 2; mt++) {
            int r0 = bm + warp_m*32 + mt*16 + (lane >> 2);
            #pragma unroll
            for (int nt = 0; nt < 8; nt++) {
                int col = bn + warp_n*64 + nt*8 + (lane & 3)*2;
                float b0 = __ldg(bias + col), b1 = __ldg(bias + col + 1);
                float2 o0 = { acc[mt][nt][0] + b0, acc[mt][nt][1] + b1 };
                float2 o1 = { acc[mt][nt][2] + b0, acc[mt][nt][3] + b1 };
                *(float2*)(outp + (size_t)r0       * DM_ + col) = o0;
                *(float2*)(outp + (size_t)(r0 + 8) * DM_ + col) = o1;
            }
        }
        return;
    }

    // QKV: bias + (LN) + fp16 split, head-major writeout.
    const int n = (bn >> 6) + warp_n;
    const float* lw = (job == 0) ? ln1w : ln2w;
    const float* lb = (job == 0) ? ln1b : ln2b;
    __half* dsth = (job == 0) ? g_qh16 : (job == 1) ? g_kh16 : g_vh16;
    __half* dstl = (job == 0) ? g_ql16 : g_kl16;
    float*  cf   = (job == 1) ? kout : vout;

    #pragma unroll
    for (int mt = 0; mt < 2; mt++) {
        #pragma unroll
        for (int rh = 0; rh < 2; rh++) {
            const int row = bm + warp_m*32 + mt*16 + (lane >> 2) + rh*8;
            const int bb_ = row >> 11;
            const int s   = row & (SQ_ - 1);
            const size_t hbase = (((size_t)(bb_ * NH_ + n)) * SQ_ + s) * DH_;

            float vals[16];
            float sum = 0.f, sq = 0.f;
            #pragma unroll
            for (int nt = 0; nt < 8; nt++) {
                int col = bn + warp_n*64 + nt*8 + (lane & 3)*2;
                float v0 = acc[mt][nt][rh*2+0] + __ldg(bias + col);
                float v1 = acc[mt][nt][rh*2+1] + __ldg(bias + col + 1);
                vals[nt*2]   = v0;
                vals[nt*2+1] = v1;
                sum += v0 + v1;
                sq  += v0*v0 + v1*v1;
            }

            if (job < 2) {
                sum += __shfl_xor_sync(0xffffffffu, sum, 1);
                sum += __shfl_xor_sync(0xffffffffu, sum, 2);
                sq  += __shfl_xor_sync(0xffffffffu, sq, 1);
                sq  += __shfl_xor_sync(0xffffffffu, sq, 2);
                float mean = sum * (1.0f/64.0f);
                float var  = sq * (1.0f/64.0f) - mean*mean;
                float rstd = rsqrtf(var + 1e-5f);
                #pragma unroll
                for (int nt = 0; nt < 8; nt++) {
                    int h = nt*8 + (lane & 3)*2;
                    vals[nt*2]   = (vals[nt*2]   - mean) * rstd * __ldg(lw + h)     + __ldg(lb + h);
                    vals[nt*2+1] = (vals[nt*2+1] - mean) * rstd * __ldg(lw + h + 1) + __ldg(lb + h + 1);
                }
            }

            #pragma unroll
            for (int nt = 0; nt < 8; nt++) {
                int h = nt*8 + (lane & 3)*2;
                float v0 = vals[nt*2], v1 = vals[nt*2+1];
                __half2 hh = __floats2half2_rn(v0, v1);
                *(__half2*)(dsth + hbase + h) = hh;
                if (job < 2) {
                    *(__half2*)(dstl + hbase + h) =
                        __floats2half2_rn(v0 - __low2float(hh), v1 - __high2float(hh));
                }
                if (job >= 1) {
                    float2 o = { v0, v1 };
                    *(float2*)(cf + (size_t)row * DM_ + bn + warp_n*64 + h) = o;
                }
            }
        }
    }
}

// ---------------------------------------------------------------------------
// Tensor-core causal flash attention (LPT + cp.async double buffer).
// z written as single fp16 hi (O-proj is now 1-term).
// ---------------------------------------------------------------------------
#define ASTR 72
#define TILEH (64*ASTR)
#define ASTAGE (3*TILEH)
#define ATTN_SMEM_BYTES (2*ASTAGE*2)   // 55296 bytes

__global__ void __launch_bounds__(128, 3)
attn_mma_kernel()
{
    extern __shared__ __half asmem[];

    const int tid  = threadIdx.x;
    const int wid  = tid >> 5;
    const int lane = tid & 31;
    const int qb = (int)gridDim.x - 1 - (int)blockIdx.x;   // LPT: heavy first
    const int n = blockIdx.y, b = blockIdx.z;
    const size_t hoff = ((size_t)(b * NH_ + n)) * SQ_ * DH_;

    const int a_off = (lane & 15) * ASTR + ((lane >> 4) << 3);
    const int b_off = ((lane & 7) + ((lane >> 4) << 3)) * ASTR + (((lane >> 3) & 1) << 3);
    const int v_off = ((lane & 7) + (((lane >> 3) & 1) << 3)) * ASTR + ((lane >> 4) << 3);

    uint32_t qfh[4][4], qfl[4][4];
    {
        const __half* qhp = g_qh16 + hoff + (size_t)qb * 64 * DH_;
        const __half* qlp = g_ql16 + hoff + (size_t)qb * 64 * DH_;
        #pragma unroll
        for (int i = 0; i < 4; i++) {
            int idx = tid + i * 128;
            int r = idx >> 3, c8 = (idx & 7) << 3;
            *(uint4*)&asmem[r*ASTR + c8]         = *(const uint4*)(qhp + (size_t)r * DH_ + c8);
            *(uint4*)&asmem[TILEH + r*ASTR + c8] = *(const uint4*)(qlp + (size_t)r * DH_ + c8);
        }
        __syncthreads();
        #pragma unroll
        for (int ks = 0; ks < 4; ks++) {
            ldsm_x4(qfh[ks], smem_u32(&asmem[(wid*16)*ASTR + ks*16 + a_off]));
            ldsm_x4(qfl[ks], smem_u32(&asmem[TILEH + (wid*16)*ASTR + ks*16 + a_off]));
        }
        __syncthreads();
    }

    const int ntiles = qb + 1;

    auto load_tile = [&](int kt, int st) {
        __half* base = asmem + st * ASTAGE;
        const __half* khp = g_kh16 + hoff + (size_t)kt * 64 * DH_;
        const __half* klp = g_kl16 + hoff + (size_t)kt * 64 * DH_;
        const __half* vhp = g_vh16 + hoff + (size_t)kt * 64 * DH_;
        #pragma unroll
        for (int i = 0; i < 4; i++) {
            int idx = tid + i * 128;
            int r = idx >> 3, c8 = (idx & 7) << 3;
            size_t go = (size_t)r * DH_ + c8;
            uint32_t so = smem_u32(base + r*ASTR + c8);
            cp_async16(so,             khp + go);
            cp_async16(so + TILEH*2,   klp + go);
            cp_async16(so + 2*TILEH*2, vhp + go);
        }
        CP_COMMIT();
    };

    float oacc[8][4];
    #pragma unroll
    for (int i = 0; i < 8; i++)
        #pragma unroll
        for (int e = 0; e < 4; e++) oacc[i][e] = 0.f;
    float m0 = -1e30f, m1 = -1e30f, l0 = 0.f, l1 = 0.f;

    const int rg0 = qb*64 + wid*16 + (lane >> 2);

    load_tile(0, 0);

    for (int kt = 0; kt < ntiles; kt++) {
        const int st = kt & 1;
        if (kt + 1 < ntiles) {
            load_tile(kt + 1, st ^ 1);
            asm volatile("cp.async.wait_group 1;" ::: "memory");
        } else {
            asm volatile("cp.async.wait_group 0;" ::: "memory");
        }
        __syncthreads();

        __half* Ksh = asmem + st * ASTAGE;
        __half* Ksl = Ksh + TILEH;
        __half* Vsh = Ksh + 2*TILEH;

        float sacc[8][4];
        #pragma unroll
        for (int i = 0; i < 8; i++)
            #pragma unroll
            for (int e = 0; e < 4; e++) sacc[i][e] = 0.f;

        #pragma unroll
        for (int ks = 0; ks < 4; ks++) {
            #pragma unroll
            for (int nbp = 0; nbp < 4; nbp++) {
                uint32_t kh4[4], kl4[4];
                ldsm_x4(kh4, smem_u32(&Ksh[(nbp*16)*ASTR + ks*16 + b_off]));
                ldsm_x4(kl4, smem_u32(&Ksl[(nbp*16)*ASTR + ks*16 + b_off]));
                #pragma unroll
                for (int h = 0; h < 2; h++) {
                    int nb = nbp*2 + h;
                    mma_f16(sacc[nb], qfh[ks], &kh4[h*2]);
                    mma_f16(sacc[nb], qfl[ks], &kh4[h*2]);
                    mma_f16(sacc[nb], qfh[ks], &kl4[h*2]);
                }
            }
        }

        if (kt == qb) {
            #pragma unroll
            for (int nb = 0; nb < 8; nb++) {
                int j = kt*64 + nb*8 + (lane & 3)*2;
                if (j     > rg0)     sacc[nb][0] = -1e30f;
                if (j + 1 > rg0)     sacc[nb][1] = -1e30f;
                if (j     > rg0 + 8) sacc[nb][2] = -1e30f;
                if (j + 1 > rg0 + 8) sacc[nb][3] = -1e30f;
            }
        }

        float t0 = -1e30f, t1 = -1e30f;
        #pragma unroll
        for (int nb = 0; nb < 8; nb++) {
            t0 = fmaxf(t0, fmaxf(sacc[nb][0], sacc[nb][1]));
            t1 = fmaxf(t1, fmaxf(sacc[nb][2], sacc[nb][3]));
        }
        t0 = fmaxf(t0, __shfl_xor_sync(0xffffffffu, t0, 1));
        t0 = fmaxf(t0, __shfl_xor_sync(0xffffffffu, t0, 2));
        t1 = fmaxf(t1, __shfl_xor_sync(0xffffffffu, t1, 1));
        t1 = fmaxf(t1, __shfl_xor_sync(0xffffffffu, t1, 2));
        float mn0 = fmaxf(m0, t0), mn1 = fmaxf(m1, t1);
        float c0 = __expf(m0 - mn0), c1 = __expf(m1 - mn1);
        m0 = mn0; m1 = mn1;

        uint32_t pah[4][4], pal[4][4];
        float rs0 = 0.f, rs1 = 0.f;
        #pragma unroll
        for (int nb = 0; nb < 8; nb++) {
            float p0 = __expf(sacc[nb][0] - mn0);
            float p1 = __expf(sacc[nb][1] - mn0);
            float p2 = __expf(sacc[nb][2] - mn1);
            float p3 = __expf(sacc[nb][3] - mn1);
            rs0 += p0 + p1; rs1 += p2 + p3;
            __half h0 = __float2half_rn(p0), h1 = __float2half_rn(p1);
            __half h2 = __float2half_rn(p2), h3 = __float2half_rn(p3);
            float q0 = p0 - __half2float(h0), q1 = p1 - __half2float(h1);
            float q2 = p2 - __half2float(h2), q3 = p3 - __half2float(h3);
            int ks = nb >> 1, sel = (nb & 1) * 2;
            pah[ks][sel]     = pk_f16x2(__half2float(h0), __half2float(h1));
            pah[ks][sel + 1] = pk_f16x2(__half2float(h2), __half2float(h3));
            pal[ks][sel]     = pk_f16x2(q0, q1);
            pal[ks][sel + 1] = pk_f16x2(q2, q3);
        }
        rs0 += __shfl_xor_sync(0xffffffffu, rs0, 1);
        rs0 += __shfl_xor_sync(0xffffffffu, rs0, 2);
        rs1 += __shfl_xor_sync(0xffffffffu, rs1, 1);
        rs1 += __shfl_xor_sync(0xffffffffu, rs1, 2);
        l0 = l0 * c0 + rs0;
        l1 = l1 * c1 + rs1;
        #pragma unroll
        for (int nb = 0; nb < 8; nb++) {
            oacc[nb][0] *= c0; oacc[nb][1] *= c0;
            oacc[nb][2] *= c1; oacc[nb][3] *= c1;
        }

        #pragma unroll
        for (int ks = 0; ks < 4; ks++) {
            #pragma unroll
            for (int nbp = 0; nbp < 4; nbp++) {
                uint32_t vh4[4];
                ldsm_x4_t(vh4, smem_u32(&Vsh[(ks*16)*ASTR + nbp*16 + v_off]));
                #pragma unroll
                for (int h = 0; h < 2; h++) {
                    int nb = nbp*2 + h;
                    mma_f16(oacc[nb], pah[ks], &vh4[h*2]);
                    mma_f16(oacc[nb], pal[ks], &vh4[h*2]);
                }
            }
        }
        __syncthreads();
    }

    float i0 = 1.0f / l0, i1 = 1.0f / l1;
    const int s0 = rg0;
    #pragma unroll
    for (int nb = 0; nb < 8; nb++) {
        int h = nb*8 + (lane & 3)*2;
        size_t z0 = (size_t)(b*SQ_ + s0    ) * DM_ + n*DH_ + h;
        size_t z1 = (size_t)(b*SQ_ + s0 + 8) * DM_ + n*DH_ + h;
        *(__half2*)(g_zh16 + z0) = __floats2half2_rn(oacc[nb][0] * i0, oacc[nb][1] * i0);
        *(__half2*)(g_zh16 + z1) = __floats2half2_rn(oacc[nb][2] * i1, oacc[nb][3] * i1);
    }
}

// ---------------------------------------------------------------------------
// Launch. Inputs: 0 x_q, 1 x_kv, 2 mask(ignored), 3 W_Q, 4 W_K, 5 W_V, 6 W_O,
// 7 b_Q, 8 b_K, 9 b_V, 10 b_O, 11 ln1_w, 12 ln1_b, 13 ln2_w, 14 ln2_b
// Output: [out (B,SQ,DM) | k_postLN (B,SK,NH,DH) | v (B,SK,NH,DH)]
// ---------------------------------------------------------------------------
extern "C" void kernel_launch(void* const* d_in, const int* in_sizes, int n_in,
                              void* d_out, int out_size)
{
    const float* x_q  = (const float*)d_in[0];
    const float* x_kv = (const float*)d_in[1];
    const float* W_Q  = (const float*)d_in[3];
    const float* W_K  = (const float*)d_in[4];
    const float* W_V  = (const float*)d_in[5];
    const float* W_O  = (const float*)d_in[6];
    const float* b_Q  = (const float*)d_in[7];
    const float* b_K  = (const float*)d_in[8];
    const float* b_V  = (const float*)d_in[9];
    const float* b_O  = (const float*)d_in[10];
    const float* ln1w = (const float*)d_in[11];
    const float* ln1b = (const float*)d_in[12];
    const float* ln2w = (const float*)d_in[13];
    const float* ln2b = (const float*)d_in[14];

    float* out  = (float*)d_out;
    float* kout = out  + HELEMS;
    float* vout = kout + HELEMS;

    cudaFuncSetAttribute(attn_mma_kernel, cudaFuncAttributeMaxDynamicSharedMemorySize,
                         ATTN_SMEM_BYTES);

    // Split inputs and weights to fp16.
    prep_split<<<dim3(512, 6), 256>>>(x_q, x_kv, W_Q, W_K, W_V, W_O);

    // Merged QKV projections with fused bias+LN+fp16-split epilogue.
    gemm3_kernel<<<dim3(DM_/128, MROWS/128, 3), 256>>>(
        b_Q, b_K, b_V, b_O, ln1w, ln1b, ln2w, ln2b, kout, vout, out, 0);

    // Causal attention -> z fp16 (LPT + double-buffered tiles)
    attn_mma_kernel<<<dim3(SQ_/64, NH_, B_), 128, ATTN_SMEM_BYTES>>>();

    // Output projection (+b_O), 1-term.
    gemm3_kernel<<<dim3(DM_/128, MROWS/128, 1), 256>>>(
        b_Q, b_K, b_V, b_O, ln1w, ln1b, ln2w, ln2b, kout, vout, out, 3);
}